// round 4
// baseline (speedup 1.0000x reference)
#include <cuda_runtime.h>
#include <cstdint>

#define Bq 4
#define Mq 8192
#define Nq 8192
#define Fq 288
#define NODESQ 16384
#define ROWSQ 32768

#define TILE_M 64
#define NTILES (ROWSQ / TILE_M)     // 512
#define KC 32
#define NCH 9                       // 288/32
#define PITCH 36
#define STAGES 3
#define NTHREADS 384
#define NCONS 256                   // warps 0..7 consumers
#define NPROD 128                   // warps 8..11 producers

// smem layout (bytes)
#define MB_OFF    0                                  // 3 stages x (full,empty) x 8B
#define TAB_OFF   128
#define STY_OFF   (TAB_OFF + TILE_M * 16 * 16)       // 16512
#define STAGE_OFF 16896
#define A_BYTES   (TILE_M * PITCH * 4)               // 9216
#define B_BYTES   (Fq * PITCH * 4)                   // 41472
#define STAGE_BYTES (A_BYTES + B_BYTES)              // 50688
#define SMEM_TOTAL (STAGE_OFF + STAGES * STAGE_BYTES) // 168960

// Scratch (static device globals — no allocations allowed)
__device__ float g_h1[(size_t)ROWSQ * Fq];      // 37.7 MB
__device__ float g_Wt1[Fq * Fq];                // W1^T, tf32-rounded, [n][k]
__device__ float g_Wt2[Fq * Fq];
__device__ int   g_deg[Bq * NODESQ];
__device__ float g_dsc[Bq * NODESQ];            // deg_out^-1/2
__device__ float g_style[Fq];                   // relu(b1): h1 of style nodes

// ---------------------------------------------------------------------------
// PTX helpers
// ---------------------------------------------------------------------------
__device__ __forceinline__ uint32_t smem_u32(const void* p) {
    uint32_t a;
    asm("{ .reg .u64 t; cvta.to.shared.u64 t, %1; cvt.u32.u64 %0, t; }"
        : "=r"(a) : "l"(p));
    return a;
}
__device__ __forceinline__ uint32_t f2tf32(float x) {
    uint32_t r;
    asm("cvt.rna.tf32.f32 %0, %1;" : "=r"(r) : "f"(x));
    return r;
}
__device__ __forceinline__ void mma_tf32(float* c, const uint32_t* a,
                                         uint32_t b0, uint32_t b1) {
    asm volatile(
        "mma.sync.aligned.m16n8k8.row.col.f32.tf32.tf32.f32 "
        "{%0,%1,%2,%3}, {%4,%5,%6,%7}, {%8,%9}, {%0,%1,%2,%3};"
        : "+f"(c[0]), "+f"(c[1]), "+f"(c[2]), "+f"(c[3])
        : "r"(a[0]), "r"(a[1]), "r"(a[2]), "r"(a[3]), "r"(b0), "r"(b1));
}
#define MBAR_INIT(a, c) \
    asm volatile("mbarrier.init.shared.b64 [%0], %1;" :: "r"(a), "r"(c) : "memory")
#define MBAR_ARRIVE(a) \
    asm volatile("mbarrier.arrive.shared.b64 _, [%0];" :: "r"(a) : "memory")

__device__ __forceinline__ void mbar_wait(uint32_t a, uint32_t ph) {
    asm volatile(
        "{\n\t.reg .pred P;\n"
        "WL%=:\n\tmbarrier.try_wait.parity.acquire.cta.shared::cta.b64 P, [%0], %1, 0x989680;\n"
        "\t@P bra WD%=;\n\tbra WL%=;\nWD%=:\n\t}"
        :: "r"(a), "r"(ph) : "memory");
}

// ---------------------------------------------------------------------------
// prep kernels
// ---------------------------------------------------------------------------
__global__ void zero_deg_kernel() {
    int i = blockIdx.x * blockDim.x + threadIdx.x;
    if (i < Bq * NODESQ) g_deg[i] = 0;
}

__global__ void hist_kernel(const int* __restrict__ idx_k1,
                            const int* __restrict__ idx_k2) {
    int e = blockIdx.x * blockDim.x + threadIdx.x;
    if (e >= Bq * Mq * 8) return;
    int b = e >> 16;     // / (Mq*8)
    atomicAdd(&g_deg[b * NODESQ + idx_k2[e]], 1);
    atomicAdd(&g_deg[b * NODESQ + Mq + idx_k1[e]], 1);
}

__global__ void dsc_kernel(const float* __restrict__ b1) {
    int i = blockIdx.x * blockDim.x + threadIdx.x;
    if (i < Bq * NODESQ) {
        int d = g_deg[i];
        g_dsc[i] = rsqrtf((float)(d > 1 ? d : 1));
    }
    if (i < Fq) g_style[i] = fmaxf(b1[i], 0.0f);
}

// Wt[n][k] = tf32(W[k][n]), tiled transpose
__global__ void transpose_tf32_kernel(const float* __restrict__ W1,
                                      const float* __restrict__ W2) {
    __shared__ float tile[32][33];
    const float* W = blockIdx.z ? W2 : W1;
    float* Wt = blockIdx.z ? g_Wt2 : g_Wt1;
    int kb = blockIdx.y * 32, nb = blockIdx.x * 32;
    int tx = threadIdx.x;
#pragma unroll
    for (int dy = threadIdx.y; dy < 32; dy += 8)
        tile[dy][tx] = W[(size_t)(kb + dy) * Fq + nb + tx];
    __syncthreads();
#pragma unroll
    for (int dy = threadIdx.y; dy < 32; dy += 8)
        Wt[(size_t)(nb + dy) * Fq + kb + tx] =
            __uint_as_float(f2tf32(tile[tx][dy]));
}

// ---------------------------------------------------------------------------
// Fused gather + tf32 GEMM layer, warp-specialized producer/consumer.
//   C[row,:] = (gathered A tile) @ Wt^T + bias  (opt ReLU)
// Producers (4 warps): gather A chunks + stream B chunks into 3-stage ring.
// Consumers (8 warps): HMMA tf32, tile 64x288, warp tile 32x72.
// ---------------------------------------------------------------------------
template <bool LAYER2, bool RELU>
__global__ void __launch_bounds__(NTHREADS, 1) fused_layer_kernel(
    const float* __restrict__ srcC,   // L1: feat_c  | L2: g_h1
    const float* __restrict__ srcS,   // L1: feat_s  | L2: unused
    const int* __restrict__ idx_k1,
    const int* __restrict__ idx_k2,
    const float* __restrict__ Wt,     // [288][288] tf32-rounded, K-contig
    const float* __restrict__ bias,
    float* __restrict__ C) {
    extern __shared__ char smem[];
    uint32_t sb = smem_u32(smem);
    const int tid = threadIdx.x;
    const int wid = tid >> 5, lane = tid & 31;

    if (tid == 0) {
#pragma unroll
        for (int s = 0; s < STAGES; s++) {
            MBAR_INIT(sb + MB_OFF + s * 16, NPROD);      // full
            MBAR_INIT(sb + MB_OFF + s * 16 + 8, NCONS);  // empty
        }
    }
    __syncthreads();

    uint4* sTab = (uint4*)(smem + TAB_OFF);
    float* sSty = (float*)(smem + STY_OFF);

    if (wid >= 8) {
        // ======================= PRODUCER (128 threads) =====================
        const int p = tid - NCONS;  // 0..127
        int st = 0, ep = 0;
        for (int t = blockIdx.x; t < NTILES; t += gridDim.x) {
            const int rowBase = t * TILE_M;
            const int b = rowBase >> 13;
            asm volatile("bar.sync 1, %0;" :: "n"(NPROD) : "memory");
            if (p < TILE_M) {
                int grow = rowBase + p;
                const float* dscB = g_dsc + b * NODESQ;
                const int4* p2 = (const int4*)(idx_k2 + (size_t)grow * 8);
                const int4* p1 = (const int4*)(idx_k1 + (size_t)grow * 8);
                int4 a2 = __ldg(p2), b2 = __ldg(p2 + 1);
                int4 a1 = __ldg(p1), b1v = __ldg(p1 + 1);
                int id2[8] = {a2.x, a2.y, a2.z, a2.w, b2.x, b2.y, b2.z, b2.w};
                int id1[8] = {a1.x, a1.y, a1.z, a1.w, b1v.x, b1v.y, b1v.z, b1v.w};
                const float* baseC = srcC + (size_t)b * Mq * Fq;
#pragma unroll
                for (int j = 0; j < 8; j++) {
                    unsigned long long ptr =
                        (unsigned long long)(baseC + (size_t)id2[j] * Fq);
                    float sc = dscB[id2[j]] * 0.25f;
                    uint4 e;
                    e.x = (uint32_t)ptr; e.y = (uint32_t)(ptr >> 32);
                    e.z = __float_as_uint(sc); e.w = 0;
                    sTab[p * 16 + j] = e;
                }
                if (LAYER2) {
                    float ss = 0.0f;
#pragma unroll
                    for (int j = 0; j < 8; j++) ss += dscB[Mq + id1[j]];
                    sSty[p] = ss * 0.25f;
                } else {
                    const float* baseS = srcS + (size_t)b * Nq * Fq;
#pragma unroll
                    for (int j = 0; j < 8; j++) {
                        unsigned long long ptr =
                            (unsigned long long)(baseS + (size_t)id1[j] * Fq);
                        float sc = dscB[Mq + id1[j]] * 0.25f;
                        uint4 e;
                        e.x = (uint32_t)ptr; e.y = (uint32_t)(ptr >> 32);
                        e.z = __float_as_uint(sc); e.w = 0;
                        sTab[p * 16 + 8 + j] = e;
                    }
                }
            }
            asm volatile("bar.sync 1, %0;" :: "n"(NPROD) : "memory");

            for (int c = 0; c < NCH; c++) {
                if (ep > 0)
                    mbar_wait(sb + MB_OFF + st * 16 + 8, (ep - 1) & 1);
                float* aS = (float*)(smem + STAGE_OFF + st * STAGE_BYTES);
                float* bS = aS + TILE_M * PITCH;

                // --- B chunk: 288 n-rows x 32 k (already tf32-rounded) ---
#pragma unroll
                for (int tI = 0; tI < 18; tI++) {
                    int i = p + tI * 128;          // 0..2303
                    int n = i >> 3, q = i & 7;
                    float4 v = __ldg((const float4*)Wt + (size_t)n * 72 + c * 8 + q);
                    *(float4*)(bS + n * PITCH + q * 4) = v;
                }

                // --- A gather: 64 rows x 32 floats ---
                float4 acc[4];
#pragma unroll
                for (int o = 0; o < 4; o++) {
                    if (LAYER2) {
                        int S = p + 128 * o;
                        int r = S >> 3, i = S & 7;
                        float ss = sSty[r];
                        float4 sv = __ldg((const float4*)g_style + c * 8 + i);
                        acc[o] = make_float4(ss * sv.x, ss * sv.y,
                                             ss * sv.z, ss * sv.w);
                    } else {
                        acc[o] = make_float4(0.f, 0.f, 0.f, 0.f);
                    }
                }
                const int NSRC = LAYER2 ? 8 : 16;
#pragma unroll
                for (int j = 0; j < NSRC; j++) {
#pragma unroll
                    for (int o = 0; o < 4; o++) {
                        int S = p + 128 * o;
                        int r = S >> 3, i = S & 7;
                        uint4 e = sTab[r * 16 + j];
                        const float4* sp = (const float4*)(
                            ((unsigned long long)e.y << 32) | (unsigned long long)e.x);
                        float4 v = __ldg(sp + c * 8 + i);
                        float sc = __uint_as_float(e.z);
                        acc[o].x = fmaf(v.x, sc, acc[o].x);
                        acc[o].y = fmaf(v.y, sc, acc[o].y);
                        acc[o].z = fmaf(v.z, sc, acc[o].z);
                        acc[o].w = fmaf(v.w, sc, acc[o].w);
                    }
                }
#pragma unroll
                for (int o = 0; o < 4; o++) {
                    int S = p + 128 * o;
                    int r = S >> 3, i = S & 7;
                    uint4 w;
                    w.x = f2tf32(acc[o].x); w.y = f2tf32(acc[o].y);
                    w.z = f2tf32(acc[o].z); w.w = f2tf32(acc[o].w);
                    *(uint4*)(aS + r * PITCH + i * 4) = w;
                }

                MBAR_ARRIVE(sb + MB_OFF + st * 16);  // full
                if (++st == STAGES) { st = 0; ep++; }
            }
        }
    } else {
        // ======================= CONSUMER (256 threads) =====================
        const int wm = wid >> 2, wn = wid & 3;       // 2 x 4 warp grid
        const int lr = lane >> 2, lc = lane & 3;
        int st = 0, ep = 0;
        for (int t = blockIdx.x; t < NTILES; t += gridDim.x) {
            const int rowBase = t * TILE_M;
            float acc[2][9][4];
#pragma unroll
            for (int i = 0; i < 2; i++)
#pragma unroll
                for (int j = 0; j < 9; j++)
#pragma unroll
                    for (int e = 0; e < 4; e++) acc[i][j][e] = 0.0f;

            for (int c = 0; c < NCH; c++) {
                mbar_wait(sb + MB_OFF + st * 16, ep & 1);  // full
                const float* aS = (const float*)(smem + STAGE_OFF + st * STAGE_BYTES);
                const float* bS = aS + TILE_M * PITCH;
#pragma unroll
                for (int ks = 0; ks < 4; ks++) {
                    int k0 = ks * 8 + lc;
                    uint32_t a[2][4];
#pragma unroll
                    for (int i = 0; i < 2; i++) {
                        int r = wm * 32 + i * 16 + lr;
                        a[i][0] = __float_as_uint(aS[r * PITCH + k0]);
                        a[i][1] = __float_as_uint(aS[(r + 8) * PITCH + k0]);
                        a[i][2] = __float_as_uint(aS[r * PITCH + k0 + 4]);
                        a[i][3] = __float_as_uint(aS[(r + 8) * PITCH + k0 + 4]);
                    }
#pragma unroll
                    for (int j = 0; j < 9; j++) {
                        int n = wn * 72 + j * 8 + lr;
                        uint32_t b0 = __float_as_uint(bS[n * PITCH + k0]);
                        uint32_t b1 = __float_as_uint(bS[n * PITCH + k0 + 4]);
                        mma_tf32(acc[0][j], a[0], b0, b1);
                        mma_tf32(acc[1][j], a[1], b0, b1);
                    }
                }
                MBAR_ARRIVE(sb + MB_OFF + st * 16 + 8);  // empty
                if (++st == STAGES) { st = 0; ep++; }
            }

            // epilogue
#pragma unroll
            for (int i = 0; i < 2; i++) {
                size_t row = (size_t)rowBase + wm * 32 + i * 16 + lr;
                float* C0 = C + row * Fq;
                float* C1 = C + (row + 8) * Fq;
#pragma unroll
                for (int j = 0; j < 9; j++) {
                    int col = wn * 72 + j * 8 + 2 * lc;
                    float bx = __ldg(bias + col), by = __ldg(bias + col + 1);
                    float2 v0, v1;
                    v0.x = acc[i][j][0] + bx; v0.y = acc[i][j][1] + by;
                    v1.x = acc[i][j][2] + bx; v1.y = acc[i][j][3] + by;
                    if (RELU) {
                        v0.x = fmaxf(v0.x, 0.f); v0.y = fmaxf(v0.y, 0.f);
                        v1.x = fmaxf(v1.x, 0.f); v1.y = fmaxf(v1.y, 0.f);
                    }
                    *(float2*)(C0 + col) = v0;
                    *(float2*)(C1 + col) = v1;
                }
            }
        }
    }
}

// ---------------------------------------------------------------------------
extern "C" void kernel_launch(void* const* d_in, const int* in_sizes, int n_in,
                              void* d_out, int out_size) {
    const float* feat_c = (const float*)d_in[0];
    const float* feat_s = (const float*)d_in[1];
    const int*   idx_k1 = (const int*)d_in[2];
    const int*   idx_k2 = (const int*)d_in[3];
    const float* W1     = (const float*)d_in[4];
    const float* b1     = (const float*)d_in[5];
    const float* W2     = (const float*)d_in[6];
    const float* b2     = (const float*)d_in[7];
    float* out = (float*)d_out;

    float* h1;  cudaGetSymbolAddress((void**)&h1,  g_h1);
    float* wt1; cudaGetSymbolAddress((void**)&wt1, g_Wt1);
    float* wt2; cudaGetSymbolAddress((void**)&wt2, g_Wt2);

    cudaFuncSetAttribute(fused_layer_kernel<false, true>,
                         cudaFuncAttributeMaxDynamicSharedMemorySize, SMEM_TOTAL);
    cudaFuncSetAttribute(fused_layer_kernel<true, false>,
                         cudaFuncAttributeMaxDynamicSharedMemorySize, SMEM_TOTAL);

    // prep
    zero_deg_kernel<<<(Bq * NODESQ + 255) / 256, 256>>>();
    hist_kernel<<<(Bq * Mq * 8 + 255) / 256, 256>>>(idx_k1, idx_k2);
    dsc_kernel<<<(Bq * NODESQ + 255) / 256, 256>>>(b1);
    {
        dim3 tg(9, 9, 2), tb(32, 8);
        transpose_tf32_kernel<<<tg, tb>>>(W1, W2);
    }

    // layer 1: h1 = relu(gather(feat) @ W1 + b1)
    fused_layer_kernel<false, true><<<148, NTHREADS, SMEM_TOTAL>>>(
        feat_c, feat_s, idx_k1, idx_k2, wt1, b1, h1);

    // layer 2: out = gather(h1, style) @ W2 + b2
    fused_layer_kernel<true, false><<<148, NTHREADS, SMEM_TOTAL>>>(
        h1, nullptr, idx_k1, idx_k2, wt2, b2, out);
}

// round 5
// speedup vs baseline: 1.0943x; 1.0943x over previous
#include <cuda_runtime.h>
#include <cstdint>

#define Bq 4
#define Mq 8192
#define Nq 8192
#define Fq 288
#define NODESQ 16384
#define ROWSQ 32768

// Scratch (static device globals — no allocations allowed)
__device__ float g_agg[(size_t)ROWSQ * Fq];     // tf32-rounded agg
__device__ float g_h1[(size_t)ROWSQ * Fq];
__device__ float g_Wt1[Fq * Fq];                // W1^T tf32-rounded, [n][k]
__device__ float g_Wt2[Fq * Fq];
__device__ int   g_deg[Bq * NODESQ];
__device__ float g_dsc[Bq * NODESQ];
__device__ float g_style[Fq];                   // relu(b1)

// ---------------------------------------------------------------------------
__device__ __forceinline__ uint32_t smem_u32(const void* p) {
    uint32_t a;
    asm("{ .reg .u64 t; cvta.to.shared.u64 t, %1; cvt.u32.u64 %0, t; }"
        : "=r"(a) : "l"(p));
    return a;
}
__device__ __forceinline__ uint32_t f2tf32(float x) {
    uint32_t r;
    asm("cvt.rna.tf32.f32 %0, %1;" : "=r"(r) : "f"(x));
    return r;
}
__device__ __forceinline__ void mma_tf32(float* c, const uint32_t* a,
                                         uint32_t b0, uint32_t b1) {
    asm volatile(
        "mma.sync.aligned.m16n8k8.row.col.f32.tf32.tf32.f32 "
        "{%0,%1,%2,%3}, {%4,%5,%6,%7}, {%8,%9}, {%0,%1,%2,%3};"
        : "+f"(c[0]), "+f"(c[1]), "+f"(c[2]), "+f"(c[3])
        : "r"(a[0]), "r"(a[1]), "r"(a[2]), "r"(a[3]), "r"(b0), "r"(b1));
}
#define CP_ASYNC16(dst, src) \
    asm volatile("cp.async.cg.shared.global [%0], [%1], 16;" \
                 :: "r"(dst), "l"(src) : "memory")
#define CP_COMMIT() asm volatile("cp.async.commit_group;" ::: "memory")
#define CP_WAIT2()  asm volatile("cp.async.wait_group 2;" ::: "memory")

// ---------------------------------------------------------------------------
// prep kernels
// ---------------------------------------------------------------------------
__global__ void zero_deg_kernel() {
    int i = blockIdx.x * blockDim.x + threadIdx.x;
    if (i < Bq * NODESQ) g_deg[i] = 0;
}

__global__ void hist_kernel(const int* __restrict__ idx_k1,
                            const int* __restrict__ idx_k2) {
    int e = blockIdx.x * blockDim.x + threadIdx.x;
    if (e >= Bq * Mq * 8) return;
    int b = e >> 16;
    atomicAdd(&g_deg[b * NODESQ + idx_k2[e]], 1);
    atomicAdd(&g_deg[b * NODESQ + Mq + idx_k1[e]], 1);
}

__global__ void dsc_kernel(const float* __restrict__ b1) {
    int i = blockIdx.x * blockDim.x + threadIdx.x;
    if (i < Bq * NODESQ) {
        int d = g_deg[i];
        g_dsc[i] = rsqrtf((float)(d > 1 ? d : 1));
    }
    if (i < Fq) g_style[i] = fmaxf(b1[i], 0.0f);
}

// Wt[n][k] = tf32(W[k][n])
__global__ void transpose_tf32_kernel(const float* __restrict__ W1,
                                      const float* __restrict__ W2) {
    __shared__ float tile[32][33];
    const float* W = blockIdx.z ? W2 : W1;
    float* Wt = blockIdx.z ? g_Wt2 : g_Wt1;
    int kb = blockIdx.y * 32, nb = blockIdx.x * 32;
    int tx = threadIdx.x;
#pragma unroll
    for (int dy = threadIdx.y; dy < 32; dy += 8)
        tile[dy][tx] = W[(size_t)(kb + dy) * Fq + nb + tx];
    __syncthreads();
#pragma unroll
    for (int dy = threadIdx.y; dy < 32; dy += 8)
        Wt[(size_t)(nb + dy) * Fq + kb + tx] =
            __uint_as_float(f2tf32(tile[tx][dy]));
}

// ---------------------------------------------------------------------------
// gathers: warp-per-row, float4 gathers; output tf32-rounded
// ---------------------------------------------------------------------------
__global__ __launch_bounds__(256) void gather1_kernel(
    const float* __restrict__ feat_c, const float* __restrict__ feat_s,
    const int* __restrict__ idx_k1, const int* __restrict__ idx_k2) {
    int wid = threadIdx.x >> 5, lane = threadIdx.x & 31;
    int row = blockIdx.x * 8 + wid;
    int b = row >> 13;
    const float* srcp = feat_c;
    float sc = 0.0f;
    if (lane < 8) {
        int i = idx_k2[row * 8 + lane];
        sc = g_dsc[b * NODESQ + i] * 0.25f;
        srcp = feat_c + ((size_t)b * Mq + i) * Fq;
    } else if (lane < 16) {
        int i = idx_k1[row * 8 + (lane - 8)];
        sc = g_dsc[b * NODESQ + Mq + i] * 0.25f;
        srcp = feat_s + ((size_t)b * Nq + i) * Fq;
    }
    unsigned long long pv = (unsigned long long)srcp;
    const float4* p[16];
    float s[16];
#pragma unroll
    for (int j = 0; j < 16; j++) {
        p[j] = (const float4*)__shfl_sync(0xffffffffu, pv, j);
        s[j] = __shfl_sync(0xffffffffu, sc, j);
    }
    uint4* outp = (uint4*)(g_agg + (size_t)row * Fq);
    for (int c = lane; c < 72; c += 32) {
        float4 a = make_float4(0.f, 0.f, 0.f, 0.f);
#pragma unroll
        for (int j = 0; j < 16; j++) {
            float4 v = __ldg(&p[j][c]);
            a.x = fmaf(v.x, s[j], a.x);
            a.y = fmaf(v.y, s[j], a.y);
            a.z = fmaf(v.z, s[j], a.z);
            a.w = fmaf(v.w, s[j], a.w);
        }
        uint4 w;
        w.x = f2tf32(a.x); w.y = f2tf32(a.y);
        w.z = f2tf32(a.z); w.w = f2tf32(a.w);
        outp[c] = w;
    }
}

__global__ __launch_bounds__(256) void gather2_kernel(
    const int* __restrict__ idx_k1, const int* __restrict__ idx_k2) {
    int wid = threadIdx.x >> 5, lane = threadIdx.x & 31;
    int row = blockIdx.x * 8 + wid;
    int b = row >> 13;
    const float* srcp = g_h1;
    float sc = 0.0f, sty = 0.0f;
    if (lane < 8) {
        int i2 = idx_k2[row * 8 + lane];
        sc = g_dsc[b * NODESQ + i2] * 0.25f;
        srcp = g_h1 + ((size_t)b * Mq + i2) * Fq;
        int i1 = idx_k1[row * 8 + lane];
        sty = g_dsc[b * NODESQ + Mq + i1] * 0.25f;
    }
    unsigned long long pv = (unsigned long long)srcp;
    const float4* p[8];
    float s[8];
    float stySum = 0.0f;
#pragma unroll
    for (int j = 0; j < 8; j++) {
        p[j] = (const float4*)__shfl_sync(0xffffffffu, pv, j);
        s[j] = __shfl_sync(0xffffffffu, sc, j);
        stySum += __shfl_sync(0xffffffffu, sty, j);
    }
    const float4* st = (const float4*)g_style;
    uint4* outp = (uint4*)(g_agg + (size_t)row * Fq);
    for (int c = lane; c < 72; c += 32) {
        float4 sv = st[c];
        float4 a;
        a.x = stySum * sv.x; a.y = stySum * sv.y;
        a.z = stySum * sv.z; a.w = stySum * sv.w;
#pragma unroll
        for (int j = 0; j < 8; j++) {
            float4 v = __ldg(&p[j][c]);
            a.x = fmaf(v.x, s[j], a.x);
            a.y = fmaf(v.y, s[j], a.y);
            a.z = fmaf(v.z, s[j], a.z);
            a.w = fmaf(v.w, s[j], a.w);
        }
        uint4 w;
        w.x = f2tf32(a.x); w.y = f2tf32(a.y);
        w.z = f2tf32(a.z); w.w = f2tf32(a.w);
        outp[c] = w;
    }
}

// ---------------------------------------------------------------------------
// tf32 mma.sync GEMM with cp.async 3-stage pipeline.
//   C[32768,288] = A @ Wt^T + bias (opt ReLU). A, Wt pre-rounded to tf32.
// CTA tile 128x144, KC=32, 256 threads (8 warps, 4m x 2n), warp tile 32x72.
// smem pitch 36 floats -> fragment LDS conflict-free (bank = lane).
// ---------------------------------------------------------------------------
#define GM 128
#define GN 144
#define GKC 32
#define GP 36
#define AFL (GM * GP)                 // 4608 floats
#define BFL (GN * GP)                 // 5184 floats
#define STFL (AFL + BFL)              // 9792 floats / stage
#define GSMEM (3 * STFL * 4)          // 117504 bytes
#define NCH 9

template <bool RELU>
__global__ void __launch_bounds__(256) gemm_tf32_kernel(
    const float* __restrict__ A, const float* __restrict__ Bt,
    const float* __restrict__ bias, float* __restrict__ C) {
    extern __shared__ float sm[];
    const int tid = threadIdx.x;
    const int wid = tid >> 5, lane = tid & 31;
    const int wm = wid >> 1, wn = wid & 1;
    const int lr = lane >> 2, lc = lane & 3;
    const int rowBase = blockIdx.x * GM;
    const int colBase = blockIdx.y * GN;

    float acc[2][9][4];
#pragma unroll
    for (int i = 0; i < 2; i++)
#pragma unroll
        for (int j = 0; j < 9; j++)
#pragma unroll
            for (int e = 0; e < 4; e++) acc[i][j][e] = 0.0f;

    const uint32_t smBase = smem_u32(sm);

    auto issue = [&](int c) {
        const int s = c % 3;
        const uint32_t aB = smBase + s * STFL * 4;
        const uint32_t bB = aB + AFL * 4;
        // A: 128 rows x 8 x 16B
#pragma unroll
        for (int t = 0; t < 4; t++) {
            int i = tid + t * 256;
            int r = i >> 3, q = i & 7;
            const float* g = A + (size_t)(rowBase + r) * Fq + c * GKC + q * 4;
            CP_ASYNC16(aB + (uint32_t)(r * GP + q * 4) * 4, g);
        }
        // B: 144 rows x 8 x 16B = 1152 chunks
#pragma unroll
        for (int t = 0; t < 5; t++) {
            int i = tid + t * 256;
            if (i < GN * 8) {
                int n = i >> 3, q = i & 7;
                const float* g = Bt + (size_t)(colBase + n) * Fq + c * GKC + q * 4;
                CP_ASYNC16(bB + (uint32_t)(n * GP + q * 4) * 4, g);
            }
        }
        CP_COMMIT();
    };

    issue(0); issue(1); issue(2);

    for (int c = 0; c < NCH; c++) {
        CP_WAIT2();
        __syncthreads();
        const int s = c % 3;
        const float* aS = sm + s * STFL;
        const float* bS = aS + AFL;
#pragma unroll
        for (int ks = 0; ks < 4; ks++) {
            const int k0 = ks * 8 + lc;
            uint32_t a[2][4];
#pragma unroll
            for (int i = 0; i < 2; i++) {
                int r = wm * 32 + i * 16 + lr;
                a[i][0] = __float_as_uint(aS[r * GP + k0]);
                a[i][1] = __float_as_uint(aS[(r + 8) * GP + k0]);
                a[i][2] = __float_as_uint(aS[r * GP + k0 + 4]);
                a[i][3] = __float_as_uint(aS[(r + 8) * GP + k0 + 4]);
            }
#pragma unroll
            for (int j = 0; j < 9; j++) {
                int n = wn * 72 + j * 8 + lr;
                uint32_t b0 = __float_as_uint(bS[n * GP + k0]);
                uint32_t b1 = __float_as_uint(bS[n * GP + k0 + 4]);
                mma_tf32(acc[0][j], a[0], b0, b1);
                mma_tf32(acc[1][j], a[1], b0, b1);
            }
        }
        __syncthreads();
        if (c + 3 < NCH) issue(c + 3);
        else CP_COMMIT();
    }

    // epilogue
#pragma unroll
    for (int i = 0; i < 2; i++) {
        size_t row = (size_t)rowBase + wm * 32 + i * 16 + lr;
        float* C0 = C + row * Fq;
        float* C1 = C + (row + 8) * Fq;
#pragma unroll
        for (int j = 0; j < 9; j++) {
            int col = colBase + wn * 72 + j * 8 + 2 * lc;
            float bx = __ldg(bias + col), by = __ldg(bias + col + 1);
            float2 v0, v1;
            v0.x = acc[i][j][0] + bx; v0.y = acc[i][j][1] + by;
            v1.x = acc[i][j][2] + bx; v1.y = acc[i][j][3] + by;
            if (RELU) {
                v0.x = fmaxf(v0.x, 0.f); v0.y = fmaxf(v0.y, 0.f);
                v1.x = fmaxf(v1.x, 0.f); v1.y = fmaxf(v1.y, 0.f);
            }
            *(float2*)(C0 + col) = v0;
            *(float2*)(C1 + col) = v1;
        }
    }
}

// ---------------------------------------------------------------------------
extern "C" void kernel_launch(void* const* d_in, const int* in_sizes, int n_in,
                              void* d_out, int out_size) {
    const float* feat_c = (const float*)d_in[0];
    const float* feat_s = (const float*)d_in[1];
    const int*   idx_k1 = (const int*)d_in[2];
    const int*   idx_k2 = (const int*)d_in[3];
    const float* W1     = (const float*)d_in[4];
    const float* b1     = (const float*)d_in[5];
    const float* W2     = (const float*)d_in[6];
    const float* b2     = (const float*)d_in[7];
    float* out = (float*)d_out;

    float* agg; cudaGetSymbolAddress((void**)&agg, g_agg);
    float* h1;  cudaGetSymbolAddress((void**)&h1,  g_h1);
    float* wt1; cudaGetSymbolAddress((void**)&wt1, g_Wt1);
    float* wt2; cudaGetSymbolAddress((void**)&wt2, g_Wt2);

    cudaFuncSetAttribute(gemm_tf32_kernel<true>,
                         cudaFuncAttributeMaxDynamicSharedMemorySize, GSMEM);
    cudaFuncSetAttribute(gemm_tf32_kernel<false>,
                         cudaFuncAttributeMaxDynamicSharedMemorySize, GSMEM);

    // prep
    zero_deg_kernel<<<(Bq * NODESQ + 255) / 256, 256>>>();
    hist_kernel<<<(Bq * Mq * 8 + 255) / 256, 256>>>(idx_k1, idx_k2);
    dsc_kernel<<<(Bq * NODESQ + 255) / 256, 256>>>(b1);
    {
        dim3 tg(9, 9, 2), tb(32, 8);
        transpose_tf32_kernel<<<tg, tb>>>(W1, W2);
    }

    dim3 ggrid(ROWSQ / GM, Fq / GN);   // 256 x 2

    // layer 1
    gather1_kernel<<<ROWSQ / 8, 256>>>(feat_c, feat_s, idx_k1, idx_k2);
    gemm_tf32_kernel<true><<<ggrid, 256, GSMEM>>>(agg, wt1, b1, h1);

    // layer 2
    gather2_kernel<<<ROWSQ / 8, 256>>>(idx_k1, idx_k2);
    gemm_tf32_kernel<false><<<ggrid, 256, GSMEM>>>(agg, wt2, b2, out);
}

// round 6
// speedup vs baseline: 1.1679x; 1.0673x over previous
#include <cuda_runtime.h>
#include <cstdint>

#define Bq 4
#define Mq 8192
#define Nq 8192
#define Fq 288
#define NODESQ 16384
#define ROWSQ 32768

// Scratch (static device globals — no allocations allowed)
__device__ float g_h1[(size_t)ROWSQ * Fq];
__device__ float g_Wt1[Fq * Fq];                // W1^T tf32-rounded, [n][k]
__device__ float g_Wt2[Fq * Fq];
__device__ int   g_deg[Bq * NODESQ];
__device__ float g_dsc[Bq * NODESQ];
__device__ float g_style[Fq];                   // relu(b1)

// ---------------------------------------------------------------------------
__device__ __forceinline__ uint32_t smem_u32(const void* p) {
    uint32_t a;
    asm("{ .reg .u64 t; cvta.to.shared.u64 t, %1; cvt.u32.u64 %0, t; }"
        : "=r"(a) : "l"(p));
    return a;
}
__device__ __forceinline__ uint32_t f2tf32(float x) {
    uint32_t r;
    asm("cvt.rna.tf32.f32 %0, %1;" : "=r"(r) : "f"(x));
    return r;
}
__device__ __forceinline__ void mma_tf32(float* c, const uint32_t* a,
                                         uint32_t b0, uint32_t b1) {
    asm volatile(
        "mma.sync.aligned.m16n8k8.row.col.f32.tf32.tf32.f32 "
        "{%0,%1,%2,%3}, {%4,%5,%6,%7}, {%8,%9}, {%0,%1,%2,%3};"
        : "+f"(c[0]), "+f"(c[1]), "+f"(c[2]), "+f"(c[3])
        : "r"(a[0]), "r"(a[1]), "r"(a[2]), "r"(a[3]), "r"(b0), "r"(b1));
}
#define CP_ASYNC16(dst, src) \
    asm volatile("cp.async.cg.shared.global [%0], [%1], 16;" \
                 :: "r"(dst), "l"(src) : "memory")
#define CP_COMMIT() asm volatile("cp.async.commit_group;" ::: "memory")
#define CP_WAIT1()  asm volatile("cp.async.wait_group 1;" ::: "memory")

// ---------------------------------------------------------------------------
// prep kernels
// ---------------------------------------------------------------------------
__global__ void zero_deg_kernel() {
    int i = blockIdx.x * blockDim.x + threadIdx.x;
    if (i < Bq * NODESQ) g_deg[i] = 0;
}

__global__ void hist_kernel(const int* __restrict__ idx_k1,
                            const int* __restrict__ idx_k2) {
    int e = blockIdx.x * blockDim.x + threadIdx.x;
    if (e >= Bq * Mq * 8) return;
    int b = e >> 16;
    atomicAdd(&g_deg[b * NODESQ + idx_k2[e]], 1);
    atomicAdd(&g_deg[b * NODESQ + Mq + idx_k1[e]], 1);
}

__global__ void dsc_kernel(const float* __restrict__ b1) {
    int i = blockIdx.x * blockDim.x + threadIdx.x;
    if (i < Bq * NODESQ) {
        int d = g_deg[i];
        g_dsc[i] = rsqrtf((float)(d > 1 ? d : 1));
    }
    if (i < Fq) g_style[i] = fmaxf(b1[i], 0.0f);
}

// Wt[n][k] = tf32(W[k][n])
__global__ void transpose_tf32_kernel(const float* __restrict__ W1,
                                      const float* __restrict__ W2) {
    __shared__ float tile[32][33];
    const float* W = blockIdx.z ? W2 : W1;
    float* Wt = blockIdx.z ? g_Wt2 : g_Wt1;
    int kb = blockIdx.y * 32, nb = blockIdx.x * 32;
    int tx = threadIdx.x;
#pragma unroll
    for (int dy = threadIdx.y; dy < 32; dy += 8)
        tile[dy][tx] = W[(size_t)(kb + dy) * Fq + nb + tx];
    __syncthreads();
#pragma unroll
    for (int dy = threadIdx.y; dy < 32; dy += 8)
        Wt[(size_t)(nb + dy) * Fq + kb + tx] =
            __uint_as_float(f2tf32(tile[tx][dy]));
}

// ---------------------------------------------------------------------------
// Fused gather + tf32 GEMM layer (inline, no warp specialization).
//   C[row,:] = (sum_j s_j * src[id_j])  @ Wt^T + bias   (opt ReLU)
// CTA: 64 rows x full N=288. KC=32, 9 chunks.
//   per chunk: gather A-chunk(c+1) regs (LDG overlaps MMA), MMA(c), STS A(c+1)
//   W streamed by cp.async, 3 stages. A double-buffered in smem (pitch 36).
// ---------------------------------------------------------------------------
#define FM 64
#define FP 36
#define FKC 32
#define FNCH 9
#define A_ST_FL (FM * FP)            // 2304 floats / stage
#define B_ST_FL (Fq * FP)            // 10368 floats / stage
#define FSMEM ((2 * A_ST_FL + 3 * B_ST_FL) * 4)   // 142848 B

template <bool LAYER2, bool RELU>
__global__ void __launch_bounds__(256) fused_layer_kernel(
    const float* __restrict__ srcC,   // L1: feat_c | L2: g_h1
    const float* __restrict__ srcS,   // L1: feat_s | L2: unused
    const int* __restrict__ idx_k1,
    const int* __restrict__ idx_k2,
    const float* __restrict__ Wt,     // [288][288] tf32-rounded, K-contig
    const float* __restrict__ bias,
    float* __restrict__ C) {
    extern __shared__ float sm[];
    const uint32_t smBase = smem_u32(sm);
    const int tid = threadIdx.x;
    const int wid = tid >> 5, lane = tid & 31;
    const int wm = wid >> 2, wn = wid & 3;       // 2m x 4n warps
    const int lr = lane >> 2, lc = lane & 3;
    const int rowBase = blockIdx.x * FM;
    const int b = rowBase >> 13;

    // ---- B (weights) cp.async streamer ----
    auto issueB = [&](int c) {
        const uint32_t bB = smBase + (uint32_t)(2 * A_ST_FL + (c % 3) * B_ST_FL) * 4;
        const float* g0 = Wt + c * FKC;
#pragma unroll
        for (int t = 0; t < 9; t++) {
            int i = tid + t * 256;               // 0..2303
            int n = i >> 3, q = i & 7;
            CP_ASYNC16(bB + (uint32_t)(n * FP + q * 4) * 4,
                       g0 + (size_t)n * Fq + q * 4);
        }
        CP_COMMIT();
    };
    issueB(0);
    issueB(1);

    // ---- per-thread gather table (registers) ----
    constexpr int NSRC = LAYER2 ? 8 : 16;
    const int row = tid >> 2;                    // 0..63
    const int q0 = tid & 3;                      // slots q0, q0+4
    const float* p[NSRC];
    float s[NSRC];
    float stySum = 0.0f;
    {
        const float* dscB = g_dsc + b * NODESQ;
        const int4* i2 = (const int4*)(idx_k2 + (size_t)(rowBase + row) * 8);
        const int4* i1 = (const int4*)(idx_k1 + (size_t)(rowBase + row) * 8);
        int4 a2 = __ldg(i2), c2 = __ldg(i2 + 1);
        int4 a1 = __ldg(i1), c1 = __ldg(i1 + 1);
        int id2[8] = {a2.x, a2.y, a2.z, a2.w, c2.x, c2.y, c2.z, c2.w};
        int id1[8] = {a1.x, a1.y, a1.z, a1.w, c1.x, c1.y, c1.z, c1.w};
#pragma unroll
        for (int j = 0; j < 8; j++) {
            p[j] = srcC + ((size_t)b * Mq + id2[j]) * Fq;
            s[j] = dscB[id2[j]] * 0.25f;
        }
        if (LAYER2) {
#pragma unroll
            for (int j = 0; j < 8; j++) stySum += dscB[Mq + id1[j]];
            stySum *= 0.25f;
        } else {
#pragma unroll
            for (int j = 0; j < 8; j++) {
                p[8 + j] = srcS + ((size_t)b * Nq + id1[j]) * Fq;
                s[8 + j] = dscB[Mq + id1[j]] * 0.25f;
            }
        }
    }

    float4 ga0, ga1;
    auto gatherChunk = [&](int c) {
        if (LAYER2) {
            float4 sv0 = __ldg((const float4*)g_style + c * 8 + q0);
            float4 sv1 = __ldg((const float4*)g_style + c * 8 + q0 + 4);
            ga0 = make_float4(stySum * sv0.x, stySum * sv0.y,
                              stySum * sv0.z, stySum * sv0.w);
            ga1 = make_float4(stySum * sv1.x, stySum * sv1.y,
                              stySum * sv1.z, stySum * sv1.w);
        } else {
            ga0 = make_float4(0.f, 0.f, 0.f, 0.f);
            ga1 = make_float4(0.f, 0.f, 0.f, 0.f);
        }
#pragma unroll
        for (int j = 0; j < NSRC; j++) {
            const float4* pj = (const float4*)p[j] + c * 8;
            float4 v0 = __ldg(pj + q0);
            float4 v1 = __ldg(pj + q0 + 4);
            float sj = s[j];
            ga0.x = fmaf(v0.x, sj, ga0.x); ga0.y = fmaf(v0.y, sj, ga0.y);
            ga0.z = fmaf(v0.z, sj, ga0.z); ga0.w = fmaf(v0.w, sj, ga0.w);
            ga1.x = fmaf(v1.x, sj, ga1.x); ga1.y = fmaf(v1.y, sj, ga1.y);
            ga1.z = fmaf(v1.z, sj, ga1.z); ga1.w = fmaf(v1.w, sj, ga1.w);
        }
    };
    auto stsChunk = [&](int c) {
        float* d = sm + (c & 1) * A_ST_FL + row * FP;
        uint4 w0, w1;
        w0.x = f2tf32(ga0.x); w0.y = f2tf32(ga0.y);
        w0.z = f2tf32(ga0.z); w0.w = f2tf32(ga0.w);
        w1.x = f2tf32(ga1.x); w1.y = f2tf32(ga1.y);
        w1.z = f2tf32(ga1.z); w1.w = f2tf32(ga1.w);
        *(uint4*)(d + q0 * 4) = w0;
        *(uint4*)(d + (q0 + 4) * 4) = w1;
    };

    // prologue: A chunk 0
    gatherChunk(0);
    stsChunk(0);

    float acc[2][9][4];
#pragma unroll
    for (int i = 0; i < 2; i++)
#pragma unroll
        for (int j = 0; j < 9; j++)
#pragma unroll
            for (int e = 0; e < 4; e++) acc[i][j][e] = 0.0f;

#pragma unroll
    for (int c = 0; c < FNCH; c++) {
        CP_WAIT1();          // own B(c) groups done (outstanding <= 1)
        __syncthreads();     // all threads: B(c)+A(c) visible; old stages free

        if (c + 2 < FNCH) issueB(c + 2);
        else CP_COMMIT();    // keep group count uniform

        if (c + 1 < FNCH) gatherChunk(c + 1);   // LDGs overlap MMA below

        const float* aS = sm + (c & 1) * A_ST_FL;
        const float* bS = sm + 2 * A_ST_FL + (c % 3) * B_ST_FL;
#pragma unroll
        for (int ks = 0; ks < 4; ks++) {
            const int k0 = ks * 8 + lc;
            uint32_t a[2][4];
#pragma unroll
            for (int i = 0; i < 2; i++) {
                int r = wm * 32 + i * 16 + lr;
                a[i][0] = __float_as_uint(aS[r * FP + k0]);
                a[i][1] = __float_as_uint(aS[(r + 8) * FP + k0]);
                a[i][2] = __float_as_uint(aS[r * FP + k0 + 4]);
                a[i][3] = __float_as_uint(aS[(r + 8) * FP + k0 + 4]);
            }
#pragma unroll
            for (int j = 0; j < 9; j++) {
                int n = wn * 72 + j * 8 + lr;
                uint32_t b0 = __float_as_uint(bS[n * FP + k0]);
                uint32_t b1 = __float_as_uint(bS[n * FP + k0 + 4]);
                mma_tf32(acc[0][j], a[0], b0, b1);
                mma_tf32(acc[1][j], a[1], b0, b1);
            }
        }

        if (c + 1 < FNCH) stsChunk(c + 1);
    }

    // ---- epilogue ----
#pragma unroll
    for (int i = 0; i < 2; i++) {
        size_t r = (size_t)rowBase + wm * 32 + i * 16 + lr;
        float* C0 = C + r * Fq;
        float* C1 = C + (r + 8) * Fq;
#pragma unroll
        for (int j = 0; j < 9; j++) {
            int col = wn * 72 + j * 8 + 2 * lc;
            float bx = __ldg(bias + col), by = __ldg(bias + col + 1);
            float2 v0, v1;
            v0.x = acc[i][j][0] + bx; v0.y = acc[i][j][1] + by;
            v1.x = acc[i][j][2] + bx; v1.y = acc[i][j][3] + by;
            if (RELU) {
                v0.x = fmaxf(v0.x, 0.f); v0.y = fmaxf(v0.y, 0.f);
                v1.x = fmaxf(v1.x, 0.f); v1.y = fmaxf(v1.y, 0.f);
            }
            *(float2*)(C0 + col) = v0;
            *(float2*)(C1 + col) = v1;
        }
    }
}

// ---------------------------------------------------------------------------
extern "C" void kernel_launch(void* const* d_in, const int* in_sizes, int n_in,
                              void* d_out, int out_size) {
    const float* feat_c = (const float*)d_in[0];
    const float* feat_s = (const float*)d_in[1];
    const int*   idx_k1 = (const int*)d_in[2];
    const int*   idx_k2 = (const int*)d_in[3];
    const float* W1     = (const float*)d_in[4];
    const float* b1     = (const float*)d_in[5];
    const float* W2     = (const float*)d_in[6];
    const float* b2     = (const float*)d_in[7];
    float* out = (float*)d_out;

    float* h1;  cudaGetSymbolAddress((void**)&h1,  g_h1);
    float* wt1; cudaGetSymbolAddress((void**)&wt1, g_Wt1);
    float* wt2; cudaGetSymbolAddress((void**)&wt2, g_Wt2);

    cudaFuncSetAttribute(fused_layer_kernel<false, true>,
                         cudaFuncAttributeMaxDynamicSharedMemorySize, FSMEM);
    cudaFuncSetAttribute(fused_layer_kernel<true, false>,
                         cudaFuncAttributeMaxDynamicSharedMemorySize, FSMEM);

    // prep
    zero_deg_kernel<<<(Bq * NODESQ + 255) / 256, 256>>>();
    hist_kernel<<<(Bq * Mq * 8 + 255) / 256, 256>>>(idx_k1, idx_k2);
    dsc_kernel<<<(Bq * NODESQ + 255) / 256, 256>>>(b1);
    {
        dim3 tg(9, 9, 2), tb(32, 8);
        transpose_tf32_kernel<<<tg, tb>>>(W1, W2);
    }

    // layer 1: h1 = relu(gather(feat) @ W1 + b1)
    fused_layer_kernel<false, true><<<ROWSQ / FM, 256, FSMEM>>>(
        feat_c, feat_s, idx_k1, idx_k2, wt1, b1, h1);

    // layer 2: out = gather(h1, style) @ W2 + b2
    fused_layer_kernel<true, false><<<ROWSQ / FM, 256, FSMEM>>>(
        h1, nullptr, idx_k1, idx_k2, wt2, b2, out);
}

// round 7
// speedup vs baseline: 1.2286x; 1.0520x over previous
#include <cuda_runtime.h>
#include <cstdint>

#define Bq 4
#define Mq 8192
#define Nq 8192
#define Fq 288
#define NODESQ 16384
#define ROWSQ 32768

// Scratch (static device globals — no allocations allowed)
__device__ float g_h1[(size_t)ROWSQ * Fq];
__device__ float g_Wt1[Fq * Fq];                // W1^T tf32-rounded, [n][k]
__device__ float g_Wt2[Fq * Fq];
__device__ int   g_deg[Bq * NODESQ];
__device__ float g_dsc[Bq * NODESQ];
__device__ float g_style[Fq];                   // relu(b1)

// ---------------------------------------------------------------------------
__device__ __forceinline__ uint32_t smem_u32(const void* p) {
    uint32_t a;
    asm("{ .reg .u64 t; cvta.to.shared.u64 t, %1; cvt.u32.u64 %0, t; }"
        : "=r"(a) : "l"(p));
    return a;
}
__device__ __forceinline__ uint32_t f2tf32(float x) {
    uint32_t r;
    asm("cvt.rna.tf32.f32 %0, %1;" : "=r"(r) : "f"(x));
    return r;
}
__device__ __forceinline__ void mma_tf32(float* c, const uint32_t* a,
                                         uint32_t b0, uint32_t b1) {
    asm volatile(
        "mma.sync.aligned.m16n8k8.row.col.f32.tf32.tf32.f32 "
        "{%0,%1,%2,%3}, {%4,%5,%6,%7}, {%8,%9}, {%0,%1,%2,%3};"
        : "+f"(c[0]), "+f"(c[1]), "+f"(c[2]), "+f"(c[3])
        : "r"(a[0]), "r"(a[1]), "r"(a[2]), "r"(a[3]), "r"(b0), "r"(b1));
}
#define CP_ASYNC16(dst, src) \
    asm volatile("cp.async.cg.shared.global [%0], [%1], 16;" \
                 :: "r"(dst), "l"(src) : "memory")
#define CP_COMMIT() asm volatile("cp.async.commit_group;" ::: "memory")
#define CP_WAIT1()  asm volatile("cp.async.wait_group 1;" ::: "memory")

// ---------------------------------------------------------------------------
// prep kernels (merged so the fused layer-1 kernel is the 4th launch for ncu)
// ---------------------------------------------------------------------------
// blocks 0..255: zero g_deg ; blocks 256..417: tf32 transpose of W1/W2
__global__ void prep0_kernel(const float* __restrict__ W1,
                             const float* __restrict__ W2) {
    if (blockIdx.x < 256) {
        int i = blockIdx.x * 256 + threadIdx.x;
        g_deg[i] = 0;
        return;
    }
    __shared__ float tile[32][33];
    int t = blockIdx.x - 256;          // 0..161
    int z = t / 81; t -= z * 81;
    int ky = t / 9, nx = t - ky * 9;
    const float* W = z ? W2 : W1;
    float* Wt = z ? g_Wt2 : g_Wt1;
    int kb = ky * 32, nb = nx * 32;
    int tx = threadIdx.x & 31, ty = threadIdx.x >> 5;
#pragma unroll
    for (int dy = ty; dy < 32; dy += 8)
        tile[dy][tx] = W[(size_t)(kb + dy) * Fq + nb + tx];
    __syncthreads();
#pragma unroll
    for (int dy = ty; dy < 32; dy += 8)
        Wt[(size_t)(nb + dy) * Fq + kb + tx] =
            __uint_as_float(f2tf32(tile[tx][dy]));
}

__global__ void hist_kernel(const int* __restrict__ idx_k1,
                            const int* __restrict__ idx_k2) {
    int e = blockIdx.x * blockDim.x + threadIdx.x;
    if (e >= Bq * Mq * 8) return;
    int b = e >> 16;
    atomicAdd(&g_deg[b * NODESQ + idx_k2[e]], 1);
    atomicAdd(&g_deg[b * NODESQ + Mq + idx_k1[e]], 1);
}

__global__ void dsc_kernel(const float* __restrict__ b1) {
    int i = blockIdx.x * blockDim.x + threadIdx.x;
    if (i < Bq * NODESQ) {
        int d = g_deg[i];
        g_dsc[i] = rsqrtf((float)(d > 1 ? d : 1));
    }
    if (i < Fq) g_style[i] = fmaxf(b1[i], 0.0f);
}

// ---------------------------------------------------------------------------
// Fused gather + tf32 GEMM layer. 512 threads, CTA = 64 rows x N=288.
// Gather lane map: row = tid>>3, q = tid&7 -> each LDG.128 covers 4 rows x
// one full aligned 128B line (rows are 1152B = 9 x 128B). KC=32, 9 chunks.
// W via 3-stage cp.async; A double-buffered (pitch 36, conflict-free).
// ---------------------------------------------------------------------------
#define FM 64
#define FP 36
#define FNCH 9
#define NT 512
// smem float offsets
#define TAB_FL 0                       // 64*16 uint2 = 2048 floats
#define STY_FL 2048                    // 64 floats
#define A_FL   2112                    // 2 * 2304
#define B_FL   (A_FL + 2 * (FM * FP))  // 6720
#define B_ST_FL (Fq * FP)              // 10368
#define FSMEM ((B_FL + 3 * B_ST_FL) * 4)   // 151296 B

template <bool LAYER2, bool RELU>
__global__ void __launch_bounds__(NT) fused_layer_kernel(
    const float* __restrict__ srcC,   // L1: feat_c | L2: g_h1
    const float* __restrict__ srcS,   // L1: feat_s | L2: unused
    const int* __restrict__ idx_k1,
    const int* __restrict__ idx_k2,
    const float* __restrict__ Wt,
    const float* __restrict__ bias,
    float* __restrict__ C) {
    extern __shared__ float sm[];
    const uint32_t smBase = smem_u32(sm);
    const int tid = threadIdx.x;
    const int wid = tid >> 5, lane = tid & 31;
    const int wm = wid >> 2, wn = wid & 3;       // 4m x 4n warps
    const int lr = lane >> 2, lc = lane & 3;
    const int row = tid >> 3;                    // 0..63
    const int q = tid & 7;                       // 16B slot in 128B chunk
    const int rowBase = blockIdx.x * FM;
    const int b = rowBase >> 13;

    uint2* tabS = (uint2*)sm;

    // ---- B (weights) cp.async streamer ----
    auto issueB = [&](int c) {
        const uint32_t bB = smBase + (uint32_t)(B_FL + (c % 3) * B_ST_FL) * 4;
        const float* g0 = Wt + c * 32;
#pragma unroll
        for (int t = 0; t < 5; t++) {
            int i = tid + t * NT;                // 0..2303
            if (i < Fq * 8) {
                int n = i >> 3, qq = i & 7;
                CP_ASYNC16(bB + (uint32_t)(n * FP + qq * 4) * 4,
                           g0 + (size_t)n * Fq + qq * 4);
            }
        }
        CP_COMMIT();
    };
    issueB(0);
    issueB(1);

    // ---- build gather table in smem (one thread per row) ----
    if (tid < FM) {
        int grow = rowBase + tid;
        const float* dscB = g_dsc + b * NODESQ;
        const int4* i2 = (const int4*)(idx_k2 + (size_t)grow * 8);
        const int4* i1 = (const int4*)(idx_k1 + (size_t)grow * 8);
        int4 a2 = __ldg(i2), c2 = __ldg(i2 + 1);
        int4 a1 = __ldg(i1), c1 = __ldg(i1 + 1);
        int id2[8] = {a2.x, a2.y, a2.z, a2.w, c2.x, c2.y, c2.z, c2.w};
        int id1[8] = {a1.x, a1.y, a1.z, a1.w, c1.x, c1.y, c1.z, c1.w};
#pragma unroll
        for (int j = 0; j < 8; j++) {
            uint32_t off = (uint32_t)(b * Mq + id2[j]) * (Fq * 4);
            float sc = dscB[id2[j]] * 0.25f;
            tabS[tid * 16 + j] = make_uint2(off, __float_as_uint(sc));
        }
        if (LAYER2) {
            float ss = 0.0f;
#pragma unroll
            for (int j = 0; j < 8; j++) ss += dscB[Mq + id1[j]];
            sm[STY_FL + tid] = ss * 0.25f;
        } else {
#pragma unroll
            for (int j = 0; j < 8; j++) {
                uint32_t off = (uint32_t)(b * Nq + id1[j]) * (Fq * 4);
                float sc = dscB[Mq + id1[j]] * 0.25f;
                tabS[tid * 16 + 8 + j] = make_uint2(off, __float_as_uint(sc));
            }
        }
    }
    __syncthreads();

    // ---- cache table in registers ----
    constexpr int NSRC = LAYER2 ? 8 : 16;
    uint32_t off[NSRC];
    float sc[NSRC];
#pragma unroll
    for (int j = 0; j < NSRC; j++) {
        uint2 e = tabS[row * 16 + j];
        off[j] = e.x;
        sc[j] = __uint_as_float(e.y);
    }
    float stySum = LAYER2 ? sm[STY_FL + row] : 0.0f;

    const char* baseC = (const char*)srcC;
    const char* baseS = (const char*)srcS;

    float4 ga;
    auto gatherChunk = [&](int c) {
        const uint32_t boff = (uint32_t)(c * 128 + q * 16);
        if (LAYER2) {
            float4 sv = __ldg((const float4*)g_style + c * 8 + q);
            ga = make_float4(stySum * sv.x, stySum * sv.y,
                             stySum * sv.z, stySum * sv.w);
        } else {
            ga = make_float4(0.f, 0.f, 0.f, 0.f);
        }
#pragma unroll
        for (int j = 0; j < NSRC; j++) {
            const char* base = (!LAYER2 && j >= 8) ? baseS : baseC;
            float4 v = __ldg((const float4*)(base + off[j] + boff));
            float sj = sc[j];
            ga.x = fmaf(v.x, sj, ga.x); ga.y = fmaf(v.y, sj, ga.y);
            ga.z = fmaf(v.z, sj, ga.z); ga.w = fmaf(v.w, sj, ga.w);
        }
    };
    auto stsChunk = [&](int c) {
        uint4 w;
        w.x = f2tf32(ga.x); w.y = f2tf32(ga.y);
        w.z = f2tf32(ga.z); w.w = f2tf32(ga.w);
        *(uint4*)(sm + A_FL + (c & 1) * (FM * FP) + row * FP + q * 4) = w;
    };

    gatherChunk(0);
    stsChunk(0);

    float acc[9][4];
#pragma unroll
    for (int j = 0; j < 9; j++)
#pragma unroll
        for (int e = 0; e < 4; e++) acc[j][e] = 0.0f;

#pragma unroll
    for (int c = 0; c < FNCH; c++) {
        CP_WAIT1();
        __syncthreads();

        if (c + 2 < FNCH) issueB(c + 2);
        else CP_COMMIT();

        if (c + 1 < FNCH) gatherChunk(c + 1);   // LDGs overlap MMA below

        const float* aS = sm + A_FL + (c & 1) * (FM * FP);
        const float* bS = sm + B_FL + (c % 3) * B_ST_FL;
#pragma unroll
        for (int ks = 0; ks < 4; ks++) {
            const int k0 = ks * 8 + lc;
            uint32_t a[4];
            int r = wm * 16 + lr;
            a[0] = __float_as_uint(aS[r * FP + k0]);
            a[1] = __float_as_uint(aS[(r + 8) * FP + k0]);
            a[2] = __float_as_uint(aS[r * FP + k0 + 4]);
            a[3] = __float_as_uint(aS[(r + 8) * FP + k0 + 4]);
#pragma unroll
            for (int j = 0; j < 9; j++) {
                int n = wn * 72 + j * 8 + lr;
                uint32_t b0 = __float_as_uint(bS[n * FP + k0]);
                uint32_t b1 = __float_as_uint(bS[n * FP + k0 + 4]);
                mma_tf32(acc[j], a, b0, b1);
            }
        }

        if (c + 1 < FNCH) stsChunk(c + 1);
    }

    // ---- epilogue ----
    {
        size_t r = (size_t)rowBase + wm * 16 + lr;
        float* C0 = C + r * Fq;
        float* C1 = C + (r + 8) * Fq;
#pragma unroll
        for (int j = 0; j < 9; j++) {
            int col = wn * 72 + j * 8 + 2 * lc;
            float bx = __ldg(bias + col), by = __ldg(bias + col + 1);
            float2 v0, v1;
            v0.x = acc[j][0] + bx; v0.y = acc[j][1] + by;
            v1.x = acc[j][2] + bx; v1.y = acc[j][3] + by;
            if (RELU) {
                v0.x = fmaxf(v0.x, 0.f); v0.y = fmaxf(v0.y, 0.f);
                v1.x = fmaxf(v1.x, 0.f); v1.y = fmaxf(v1.y, 0.f);
            }
            *(float2*)(C0 + col) = v0;
            *(float2*)(C1 + col) = v1;
        }
    }
}

// ---------------------------------------------------------------------------
extern "C" void kernel_launch(void* const* d_in, const int* in_sizes, int n_in,
                              void* d_out, int out_size) {
    const float* feat_c = (const float*)d_in[0];
    const float* feat_s = (const float*)d_in[1];
    const int*   idx_k1 = (const int*)d_in[2];
    const int*   idx_k2 = (const int*)d_in[3];
    const float* W1     = (const float*)d_in[4];
    const float* b1     = (const float*)d_in[5];
    const float* W2     = (const float*)d_in[6];
    const float* b2     = (const float*)d_in[7];
    float* out = (float*)d_out;

    float* h1;  cudaGetSymbolAddress((void**)&h1,  g_h1);
    float* wt1; cudaGetSymbolAddress((void**)&wt1, g_Wt1);
    float* wt2; cudaGetSymbolAddress((void**)&wt2, g_Wt2);

    cudaFuncSetAttribute(fused_layer_kernel<false, true>,
                         cudaFuncAttributeMaxDynamicSharedMemorySize, FSMEM);
    cudaFuncSetAttribute(fused_layer_kernel<true, false>,
                         cudaFuncAttributeMaxDynamicSharedMemorySize, FSMEM);

    // prep (3 launches so fused layer 1 is the 4th launch — ncu profiles it)
    prep0_kernel<<<256 + 162, 256>>>(W1, W2);
    hist_kernel<<<(Bq * Mq * 8 + 255) / 256, 256>>>(idx_k1, idx_k2);
    dsc_kernel<<<(Bq * NODESQ + 255) / 256, 256>>>(b1);

    // layer 1: h1 = relu(gather(feat) @ W1 + b1)
    fused_layer_kernel<false, true><<<ROWSQ / FM, NT, FSMEM>>>(
        feat_c, feat_s, idx_k1, idx_k2, wt1, b1, h1);

    // layer 2: out = gather(h1, style) @ W2 + b2
    fused_layer_kernel<true, false><<<ROWSQ / FM, NT, FSMEM>>>(
        h1, nullptr, idx_k1, idx_k2, wt2, b2, out);
}